// round 11
// baseline (speedup 1.0000x reference)
#include <cuda_runtime.h>
#include <cuda_fp16.h>
#include <math.h>
#include <stdint.h>

#define N_NODES 100000
#define HALF_NODES 50000
#define N_EDGES 6400000
#define THETA   1.0f
#define EQUIL_STEPS 100
#define REC_STEPS   200
#define TOTAL_STEPS (EQUIL_STEPS + REC_STEPS)
#define GRID_CTAS   148
#define CTA_THREADS 704            // 22 warps; 676 active node-threads
#define NPC         676            // nodes per CTA (148*676 = 100048)
#define MAXDEG_H    96             // per half; Poisson(32): P(>96) ~ 1e-20
#define SMEM_BYTES  (N_NODES * 2)  // 200000 B fp16 state
#define HALF_BYTES  (HALF_NODES * 2)            // 100000 B per staged half
#define ELL_CTA_WORDS (NPC * MAXDEG_H)          // 64896 words per CTA per half
#define ELL_HALF_WORDS ((size_t)GRID_CTAS * ELL_CTA_WORDS)
#define ELL_TOTAL  (2 * ELL_HALF_WORDS)         // ~19.2M words = 76.8MB

// ---------------- device scratch (sanctioned: __device__ globals) -------------
// Packed edge: bits[0:17)=src, bits[16:32)=fp16 weight (bit0 forced 0; bit16 shared).
// Group-of-4 ELL per CTA per src-half:
//   g_ell[ h*ELL_HALF_WORDS + c*ELL_CTA_WORDS + (j>>2)*(NPC*4) + r*4 + (j&3) ]
__device__ unsigned g_ell[ELL_TOTAL];
__device__ int      g_deg[N_NODES];             // total degree (for sort)
__device__ int      g_cur[2][N_NODES];          // per-half cursors == per-half degree
__device__ int      g_slot[N_NODES];            // node -> slot within its CTA
__device__ int      g_pnode[GRID_CTAS * NPC];   // CTA slot -> node
__device__ __half   g_state[2][N_NODES];        // double-buffered fp16 state
__device__ int      g_is64;
__device__ unsigned g_bar;

// ---------------- small PTX helpers -------------------------------------------
__device__ __forceinline__ unsigned smem_u32(const void* p) {
    unsigned a;
    asm("{ .reg .u64 t; cvta.to.shared.u64 t, %1; cvt.u32.u64 %0, t; }"
        : "=r"(a) : "l"(p));
    return a;
}
__device__ __forceinline__ unsigned ctarank() {
    unsigned r; asm("mov.u32 %0, %%cluster_ctarank;" : "=r"(r)); return r;
}
__device__ __forceinline__ void mbar_init(unsigned a, unsigned cnt) {
    asm volatile("mbarrier.init.shared.b64 [%0], %1;" :: "r"(a), "r"(cnt) : "memory");
}
__device__ __forceinline__ void mbar_expect(unsigned a, unsigned bytes) {
    asm volatile("mbarrier.arrive.expect_tx.shared.b64 _, [%0], %1;"
                 :: "r"(a), "r"(bytes) : "memory");
}
__device__ __forceinline__ void mbar_wait(unsigned a, unsigned parity) {
    asm volatile(
        "{\n\t.reg .pred P;\n\t"
        "WL_%=:\n\t"
        "mbarrier.try_wait.parity.acquire.cta.shared::cta.b64 P, [%0], %1, 0x989680;\n\t"
        "@P bra.uni WD_%=;\n\t"
        "bra.uni WL_%=;\n\t"
        "WD_%=:\n\t}"
        :: "r"(a), "r"(parity) : "memory");
}
__device__ __forceinline__ void bulk_mc(unsigned dst, const void* src,
                                        unsigned bytes, unsigned mbar,
                                        unsigned short mask) {
    asm volatile(
        "cp.async.bulk.shared::cluster.global.mbarrier::complete_tx::bytes"
        ".multicast::cluster [%0], [%1], %2, [%3], %4;"
        :: "r"(dst), "l"(src), "r"(bytes), "r"(mbar), "h"(mask) : "memory");
}

// ---------------- dtype detection ---------------------------------------------
__global__ void detect_kernel(const int* __restrict__ ei32) {
    int all_zero = 1;
    for (int k = 0; k < 128; k++)
        if (ei32[2 * k + 1] != 0) { all_zero = 0; break; }
    g_is64 = all_zero;
}

// ---------------- preprocessing ------------------------------------------------
__global__ void zero_kernel() {
    int i = blockIdx.x * blockDim.x + threadIdx.x;
    if (i < N_NODES) { g_deg[i] = 0; g_cur[0][i] = 0; g_cur[1][i] = 0; }
    if (i == 0) g_bar = 0u;
}

__global__ void ell_zero_kernel() {                  // zero pad => w=0 edges
    size_t i = (size_t)blockIdx.x * blockDim.x + threadIdx.x;
    uint4* p = (uint4*)g_ell;
    if (i < ELL_TOTAL / 4) p[i] = make_uint4(0u, 0u, 0u, 0u);
}

__device__ __forceinline__ int load_idx(const int* __restrict__ ei32,
                                        long long pos, int is64) {
    return is64 ? ei32[2 * pos] : ei32[pos];
}

__global__ void hist_kernel(const int* __restrict__ ei32) {
    long long i = blockIdx.x * blockDim.x + threadIdx.x;   // exact grid
    int is64 = g_is64;
    int d = load_idx(ei32, (long long)N_EDGES + i, is64);
    if ((unsigned)d < N_NODES) atomicAdd(&g_deg[d], 1);
}

// Per-CTA counting sort of nodes by clamped total degree.
__global__ __launch_bounds__(1024) void sort_kernel() {
    __shared__ int off[2 * MAXDEG_H + 1];
    int c = blockIdx.x, t = threadIdx.x;
    int nbeg = c * NPC;
    int count = N_NODES - nbeg; if (count > NPC) count = NPC;

    for (int i = t; i <= 2 * MAXDEG_H; i += 1024) off[i] = 0;
    __syncthreads();

    int n = nbeg + t, d = 0;
    if (t < count) {
        d = g_deg[n]; if (d > 2 * MAXDEG_H) d = 2 * MAXDEG_H;
        atomicAdd(&off[d], 1);
    }
    __syncthreads();
    if (t == 0) {
        int run = 0;
        for (int i = 0; i <= 2 * MAXDEG_H; i++) { int h = off[i]; off[i] = run; run += h; }
    }
    __syncthreads();
    if (t < count) {
        int slot = atomicAdd(&off[d], 1);
        g_slot[n] = slot;
        g_pnode[nbeg + slot] = n;
    }
}

__global__ void scatter_kernel(const int* __restrict__ ei32,
                               const float* __restrict__ W) {
    long long i = blockIdx.x * blockDim.x + threadIdx.x;   // exact grid
    int is64 = g_is64;
    int s = load_idx(ei32, i, is64);
    int d = load_idx(ei32, (long long)N_EDGES + i, is64);
    if ((unsigned)d >= N_NODES || (unsigned)s >= N_NODES) return;
    int c = d / NPC;
    int r = g_slot[d];
    int h = (s >= HALF_NODES) ? 1 : 0;
    int j = atomicAdd(&g_cur[h][d], 1);
    if (j < MAXDEG_H) {
        unsigned hw = (unsigned)__half_as_ushort(__float2half_rn(W[i]));
        hw = (hw + (hw & 1u)) & 0xFFFEu;            // round mantissa LSB away
        unsigned pk = (unsigned)s | (hw << 16);
        size_t idx = (size_t)h * ELL_HALF_WORDS + (size_t)c * ELL_CTA_WORDS
                   + (size_t)(j >> 2) * (NPC * 4) + (size_t)r * 4 + (j & 3);
        g_ell[idx] = pk;
    }
}

__global__ void init_state_kernel(const float* __restrict__ x) {
    int i = blockIdx.x * blockDim.x + threadIdx.x;
    if (i < N_NODES) g_state[0][i] = __float2half_rn(x[i]);
}

// ---------------- persistent simulation kernel --------------------------------
__device__ __forceinline__ float dec_edge(unsigned v, const __half* __restrict__ sh) {
    unsigned s = v & 0x1FFFFu;
    __half  w = __ushort_as_half((unsigned short)((v >> 16) & 0xFFFEu));
    return __half2float(w) * __half2float(sh[s]);
}

__global__ __launch_bounds__(CTA_THREADS, 1)
void sim_kernel(float* __restrict__ out) {
    extern __shared__ __half s_sh[];                 // 100000 halves = 200000 B
    __shared__ __align__(8) unsigned long long s_mbar[2];   // [0]=lo half, [1]=hi half
    const int tid  = threadIdx.x;
    const int cta  = blockIdx.x;
    const unsigned rank = ctarank();                 // 0/1 within cluster of 2
    const unsigned mb_lo = smem_u32(&s_mbar[0]);
    const unsigned mb_hi = smem_u32(&s_mbar[1]);
    const unsigned sbase = smem_u32(s_sh);

    const int base = cta * NPC;
    int count = N_NODES - base; if (count > NPC) count = NPC;
    const bool active = tid < count;

    int n = 0, g0 = 0, g1 = 0;
    if (active) {
        n = g_pnode[base + tid];
        int d0 = g_cur[0][n]; if (d0 > MAXDEG_H) d0 = MAXDEG_H;
        int d1 = g_cur[1][n]; if (d1 > MAXDEG_H) d1 = MAXDEG_H;
        g0 = (d0 + 3) >> 2;
        g1 = (d1 + 3) >> 2;
    }
    const uint4* __restrict__ e_lo =
        (const uint4*)(g_ell + (size_t)cta * ELL_CTA_WORDS) + tid;
    const uint4* __restrict__ e_hi =
        (const uint4*)(g_ell + ELL_HALF_WORDS + (size_t)cta * ELL_CTA_WORDS) + tid;

    if (tid == 0) { mbar_init(mb_lo, 1); mbar_init(mb_hi, 1); }
    __syncthreads();
    asm volatile("barrier.cluster.arrive.aligned;" ::: "memory");
    asm volatile("barrier.cluster.wait.aligned;"   ::: "memory");

    for (int t = 0; t < TOTAL_STEPS; t++) {
        const unsigned parity = (unsigned)(t & 1);
        // ---- stage state via TMA multicast: rank r loads half r for BOTH CTAs
        if (tid == 0) {
            asm volatile("fence.proxy.async;" ::: "memory");
            mbar_expect(mb_lo, HALF_BYTES);
            mbar_expect(mb_hi, HALF_BYTES);
            const __half* src = g_state[t & 1];
            if (rank == 0)
                bulk_mc(sbase, src, HALF_BYTES, mb_lo, (unsigned short)3);
            else
                bulk_mc(sbase + HALF_BYTES, src + HALF_NODES, HALF_BYTES,
                        mb_hi, (unsigned short)3);
        }

        float a0 = 0.0f, a1 = 0.0f;
        // ---- gather lo-half edges as soon as lo state lands
        mbar_wait(mb_lo, parity);
        if (active) {
            const uint4* pe = e_lo;
            for (int g = 0; g < g0; g++) {
                uint4 v = __ldg(pe); pe += NPC;
                a0 += dec_edge(v.x, s_sh); a1 += dec_edge(v.y, s_sh);
                a0 += dec_edge(v.z, s_sh); a1 += dec_edge(v.w, s_sh);
            }
        }
        // ---- hi half (overlapped with the lo gather above)
        mbar_wait(mb_hi, parity);
        if (active) {
            const uint4* pe = e_hi;
            for (int g = 0; g < g1; g++) {
                uint4 v = __ldg(pe); pe += NPC;
                a0 += dec_edge(v.x, s_sh); a1 += dec_edge(v.y, s_sh);
                a0 += dec_edge(v.z, s_sh); a1 += dec_edge(v.w, s_sh);
            }
            float val = 1.0f / (1.0f + __expf(THETA - (a0 + a1)));
            g_state[(t + 1) & 1][n] = __float2half_rn(val);
            if (t >= EQUIL_STEPS)
                __stcs(out + (size_t)(t - EQUIL_STEPS) * N_NODES + n, val);
        }

        // ---- software grid barrier (all 148 CTAs co-resident, 1/SM)
        __syncthreads();
        if (tid == 0) {
            __threadfence();                         // publish s_new / raster
            atomicAdd(&g_bar, 1u);
            unsigned target = (unsigned)GRID_CTAS * (unsigned)(t + 1);
            while (*(volatile unsigned*)&g_bar < target) { }
            __threadfence();                         // observe peers' s_new
        }
        __syncthreads();
    }

    asm volatile("barrier.cluster.arrive.aligned;" ::: "memory");
    asm volatile("barrier.cluster.wait.aligned;"   ::: "memory");
}

// ---------------- launch --------------------------------------------------------
extern "C" void kernel_launch(void* const* d_in, const int* in_sizes, int n_in,
                              void* d_out, int out_size) {
    const float* x    = (const float*)d_in[0];   // (N_NODES, 1) f32
    const float* W    = (const float*)d_in[1];   // (N_EDGES,)   f32
    const int*   ei32 = (const int*)d_in[2];     // (2, N_EDGES) int32 view (int64 detected)
    float* out = (float*)d_out;                   // (REC_STEPS, N_NODES) f32

    cudaFuncSetAttribute(sim_kernel,
                         cudaFuncAttributeMaxDynamicSharedMemorySize, SMEM_BYTES);

    // ---- build packed dual-half ELL (per launch; deterministic)
    detect_kernel<<<1, 1>>>(ei32);
    zero_kernel<<<(N_NODES + 255) / 256, 256>>>();
    ell_zero_kernel<<<(int)((ELL_TOTAL / 4 + 255) / 256), 256>>>();
    hist_kernel<<<N_EDGES / 256, 256>>>(ei32);
    sort_kernel<<<GRID_CTAS, 1024>>>();
    scatter_kernel<<<N_EDGES / 256, 256>>>(ei32, W);
    init_state_kernel<<<(N_NODES + 255) / 256, 256>>>(x);

    // ---- persistent sim kernel: 74 clusters x 2 CTAs (multicast staging)
    cudaLaunchConfig_t cfg = {};
    cfg.gridDim  = dim3(GRID_CTAS, 1, 1);
    cfg.blockDim = dim3(CTA_THREADS, 1, 1);
    cfg.dynamicSmemBytes = SMEM_BYTES;
    cfg.stream = 0;
    cudaLaunchAttribute attrs[1];
    attrs[0].id = cudaLaunchAttributeClusterDimension;
    attrs[0].val.clusterDim.x = 2;
    attrs[0].val.clusterDim.y = 1;
    attrs[0].val.clusterDim.z = 1;
    cfg.attrs = attrs;
    cfg.numAttrs = 1;
    cudaLaunchKernelEx(&cfg, sim_kernel, out);
}

// round 13
// speedup vs baseline: 1.1134x; 1.1134x over previous
#include <cuda_runtime.h>
#include <cuda_fp16.h>
#include <math.h>
#include <stdint.h>

#define N_NODES 100000
#define N_EDGES 6400000
#define THETA   1.0f
#define EQUIL_STEPS 100
#define REC_STEPS   200
#define TOTAL_STEPS (EQUIL_STEPS + REC_STEPS)
#define GRID_CTAS   148
#define CTA_THREADS 704            // 22 warps; 676 active node-threads
#define NPC         676            // slots per CTA (148*676 = 100048 >= 100000)
#define MAXDEG      160            // Poisson(64): P(deg>160) ~ 1e-23
#define SMEM_BYTES  (N_NODES * 2)  // 200000 B fp16 state
#define ELL_CTA_WORDS (NPC * MAXDEG)                 // 108160 words per CTA
#define ELL_TOTAL  ((size_t)GRID_CTAS * ELL_CTA_WORDS)   // 64 MB

// ---------------- device scratch (sanctioned: __device__ globals) -------------
// Packed edge: bits[0:17)=src, bits[16:32)=fp16 weight (bit0 forced 0; bit16 shared).
// Group-of-4 ELL: edge j of slot r in CTA c at
//   c*ELL_CTA_WORDS + (j>>2)*(NPC*4) + r*4 + (j&3)
__device__ unsigned g_ell[ELL_TOTAL];
__device__ int      g_deg[N_NODES];
__device__ int      g_cur[N_NODES];
__device__ int      g_pos[N_NODES];              // node -> global sorted position
__device__ int      g_pnode[GRID_CTAS * NPC];    // (cta,slot) -> node
__device__ int      g_bin[MAXDEG + 1];           // global degree histogram / offsets
__device__ __half   g_state[2][N_NODES];
__device__ int      g_is64;
__device__ unsigned g_bar;

// ---------------- small helpers ------------------------------------------------
__device__ __forceinline__ unsigned smem_u32(const void* p) {
    unsigned a;
    asm("{ .reg .u64 t; cvta.to.shared.u64 t, %1; cvt.u32.u64 %0, t; }"
        : "=r"(a) : "l"(p));
    return a;
}
__device__ __forceinline__ void cp16(unsigned dst, const void* src) {
    asm volatile("cp.async.cg.shared.global [%0], [%1], 16;"
                 :: "r"(dst), "l"(src) : "memory");
}

// ---------------- dtype detection ---------------------------------------------
__global__ void detect_kernel(const int* __restrict__ ei32) {
    int all_zero = 1;
    for (int k = 0; k < 128; k++)
        if (ei32[2 * k + 1] != 0) { all_zero = 0; break; }
    g_is64 = all_zero;
}

// ---------------- preprocessing ------------------------------------------------
__global__ void zero_kernel() {
    int i = blockIdx.x * blockDim.x + threadIdx.x;
    if (i < N_NODES) { g_deg[i] = 0; g_cur[i] = 0; }
    if (i <= MAXDEG) g_bin[i] = 0;
    if (i == 0) g_bar = 0u;
}

__global__ void ell_zero_kernel() {                  // zero pad => w=0 edges
    size_t i = (size_t)blockIdx.x * blockDim.x + threadIdx.x;
    uint4* p = (uint4*)g_ell;
    if (i < ELL_TOTAL / 4) p[i] = make_uint4(0u, 0u, 0u, 0u);
}

__device__ __forceinline__ int load_idx(const int* __restrict__ ei32,
                                        long long pos, int is64) {
    return is64 ? ei32[2 * pos] : ei32[pos];
}

__global__ void hist_kernel(const int* __restrict__ ei32) {
    long long i = blockIdx.x * blockDim.x + threadIdx.x;   // exact grid
    int is64 = g_is64;
    int d = load_idx(ei32, (long long)N_EDGES + i, is64);
    if ((unsigned)d < N_NODES) atomicAdd(&g_deg[d], 1);
}

// Global degree histogram (smem-privatized).
__global__ __launch_bounds__(1024) void ghist_kernel() {
    __shared__ int h[MAXDEG + 1];
    int t = threadIdx.x;
    for (int i = t; i <= MAXDEG; i += 1024) h[i] = 0;
    __syncthreads();
    int n = blockIdx.x * 1024 + t;
    if (n < N_NODES) {
        int d = g_deg[n]; if (d > MAXDEG) d = MAXDEG;
        atomicAdd(&h[d], 1);
    }
    __syncthreads();
    for (int i = t; i <= MAXDEG; i += 1024)
        if (h[i]) atomicAdd(&g_bin[i], h[i]);
}

__global__ void gprefix_kernel() {                   // 161 bins, 1 thread
    int run = 0;
    for (int i = 0; i <= MAXDEG; i++) { int h = g_bin[i]; g_bin[i] = run; run += h; }
}

// Assign node -> global sorted position p; CTA = p%148, slot = p/148.
__global__ void place_kernel() {
    int n = blockIdx.x * blockDim.x + threadIdx.x;
    if (n >= N_NODES) return;
    int d = g_deg[n]; if (d > MAXDEG) d = MAXDEG;
    int p = atomicAdd(&g_bin[d], 1);
    g_pos[n] = p;
    g_pnode[(p % GRID_CTAS) * NPC + (p / GRID_CTAS)] = n;
}

__global__ void scatter_kernel(const int* __restrict__ ei32,
                               const float* __restrict__ W) {
    long long i = blockIdx.x * blockDim.x + threadIdx.x;   // exact grid
    int is64 = g_is64;
    int s = load_idx(ei32, i, is64);
    int d = load_idx(ei32, (long long)N_EDGES + i, is64);
    if ((unsigned)d >= N_NODES || (unsigned)s >= N_NODES) return;
    int p = g_pos[d];
    int c = p % GRID_CTAS;
    int r = p / GRID_CTAS;
    int j = atomicAdd(&g_cur[d], 1);
    if (j < MAXDEG) {
        unsigned hw = (unsigned)__half_as_ushort(__float2half_rn(W[i]));
        hw = (hw + (hw & 1u)) & 0xFFFEu;            // round mantissa LSB away
        unsigned pk = (unsigned)s | (hw << 16);
        size_t idx = (size_t)c * ELL_CTA_WORDS
                   + (size_t)(j >> 2) * (NPC * 4) + (size_t)r * 4 + (j & 3);
        g_ell[idx] = pk;
    }
}

__global__ void init_state_kernel(const float* __restrict__ x) {
    int i = blockIdx.x * blockDim.x + threadIdx.x;
    if (i < N_NODES) g_state[0][i] = __float2half_rn(x[i]);
}

// ---------------- persistent simulation kernel --------------------------------
__device__ __forceinline__ float dec_edge(unsigned v, const __half* __restrict__ sh) {
    unsigned s = v & 0x1FFFFu;
    __half  w = __ushort_as_half((unsigned short)((v >> 16) & 0xFFFEu));
    return __half2float(w) * __half2float(sh[s]);
}

__global__ __launch_bounds__(CTA_THREADS, 1)
void sim_kernel(float* __restrict__ out) {
    extern __shared__ __half s_sh[];                 // 100000 halves = 200000 B
    const int tid = threadIdx.x;
    const int cta = blockIdx.x;
    const unsigned sbase = smem_u32(s_sh);

    // slot tid of CTA cta holds sorted position p = tid*148 + cta
    const bool active = (tid < NPC) && (tid * GRID_CTAS + cta < N_NODES);
    int n = 0, groups = 0;
    if (active) {
        n = g_pnode[cta * NPC + tid];
        int d = g_deg[n]; if (d > MAXDEG) d = MAXDEG;
        groups = (d + 3) >> 2;
    }
    const uint4* __restrict__ e0 =
        (const uint4*)(g_ell + (size_t)cta * ELL_CTA_WORDS) + tid;

    for (int t = 0; t < TOTAL_STEPS; t++) {
        // ---- stage full fp16 state into smem via cp.async (L2 path, no STS)
        const uint4* sv = (const uint4*)g_state[t & 1];
        for (int i = tid; i < (N_NODES * 2 / 16); i += CTA_THREADS)  // 12500
            cp16(sbase + i * 16, sv + i);
        asm volatile("cp.async.commit_group;" ::: "memory");
        asm volatile("cp.async.wait_group 0;" ::: "memory");
        __syncthreads();

        if (active) {
            const uint4* pe = e0;
            float a0 = 0.0f, a1 = 0.0f;
            for (int g = 0; g < groups; g++) {
                uint4 v = __ldg(pe); pe += NPC;      // 4 edges, one LDG.128
                a0 += dec_edge(v.x, s_sh); a1 += dec_edge(v.y, s_sh);
                a0 += dec_edge(v.z, s_sh); a1 += dec_edge(v.w, s_sh);
            }
            float val = 1.0f / (1.0f + __expf(THETA - (a0 + a1)));
            g_state[(t + 1) & 1][n] = __float2half_rn(val);
            if (t >= EQUIL_STEPS)
                __stcs(out + (size_t)(t - EQUIL_STEPS) * N_NODES + n, val);
        }

        // ---- software grid barrier (all 148 CTAs co-resident, 1/SM)
        __syncthreads();
        if (tid == 0) {
            __threadfence();                         // publish s_new / raster
            atomicAdd(&g_bar, 1u);
            unsigned target = (unsigned)GRID_CTAS * (unsigned)(t + 1);
            while (*(volatile unsigned*)&g_bar < target) { }
            __threadfence();                         // observe peers' s_new
        }
        __syncthreads();
    }
}

// ---------------- launch --------------------------------------------------------
extern "C" void kernel_launch(void* const* d_in, const int* in_sizes, int n_in,
                              void* d_out, int out_size) {
    const float* x    = (const float*)d_in[0];   // (N_NODES, 1) f32
    const float* W    = (const float*)d_in[1];   // (N_EDGES,)   f32
    const int*   ei32 = (const int*)d_in[2];     // (2, N_EDGES) int32 view (int64 detected)
    float* out = (float*)d_out;                   // (REC_STEPS, N_NODES) f32

    cudaFuncSetAttribute(sim_kernel,
                         cudaFuncAttributeMaxDynamicSharedMemorySize, SMEM_BYTES);

    // ---- build packed ELL with global stratified degree sort (per launch)
    detect_kernel<<<1, 1>>>(ei32);
    zero_kernel<<<(N_NODES + 255) / 256, 256>>>();
    ell_zero_kernel<<<(int)((ELL_TOTAL / 4 + 255) / 256), 256>>>();
    hist_kernel<<<N_EDGES / 256, 256>>>(ei32);
    ghist_kernel<<<(N_NODES + 1023) / 1024, 1024>>>();
    gprefix_kernel<<<1, 1>>>();
    place_kernel<<<(N_NODES + 255) / 256, 256>>>();
    scatter_kernel<<<N_EDGES / 256, 256>>>(ei32, W);
    init_state_kernel<<<(N_NODES + 255) / 256, 256>>>(x);

    // ---- one persistent kernel runs all 300 steps
    sim_kernel<<<GRID_CTAS, CTA_THREADS, SMEM_BYTES>>>(out);
}